// round 7
// baseline (speedup 1.0000x reference)
#include <cuda_runtime.h>
#include <math.h>

#define HIDC 128
#define NMAX 100000
#define EMAX 3200000

// ---------------- scratch (no allocation allowed) ----------------
__device__ __align__(16) float g_bufA[(size_t)NMAX * HIDC];   // 51.2 MB
__device__ __align__(16) float g_bufB[(size_t)NMAX * HIDC];   // 51.2 MB
__device__ int   g_cnt[NMAX];
__device__ int   g_rowptr[NMAX + 1];
__device__ int   g_cursor[NMAX];
__device__ float g_dinv[NMAX];
__device__ int   g_srccsr[EMAX];                // 12.8 MB CSR (by dst) of src ids
__device__ int   g_is64;                        // edge_index dtype flag

// ---------------- dtype detection ----------------
// If edge_index is int64 (little-endian, values < 2^31), every odd 32-bit word
// in the first 2E words (the src array) is 0. If int32, those words are random
// node ids. Sample 1024 odd words: all-zero => int64.
__global__ void detect_k(const unsigned int* __restrict__ w, int E) {
    __shared__ int found;
    if (threadIdx.x == 0) found = 0;
    __syncthreads();
    unsigned stride = (unsigned)E / 1024u;
    if (stride == 0) stride = 1;
    #pragma unroll
    for (int i = 0; i < 4; i++) {
        unsigned q = ((unsigned)threadIdx.x * 4u + i) * stride;
        if (q < (unsigned)E) {
            if (w[2u * q + 1u] != 0u) found = 1;
        }
    }
    __syncthreads();
    if (threadIdx.x == 0) g_is64 = found ? 0 : 1;
}

// which: 0 = src, 1 = dst. Works for both int32 and int64 storage.
__device__ __forceinline__ int load_idx(const int* __restrict__ w, int E, int e, int which) {
    size_t elem = (size_t)which * E + e;
    return g_is64 ? w[2 * elem] : w[elem];
}

// ---------------- setup kernels ----------------
__global__ void zero_cnt_k(int N) {
    int i = blockIdx.x * blockDim.x + threadIdx.x;
    if (i < N) g_cnt[i] = 0;
}

__global__ void count_k(const int* __restrict__ ew, int E, int N) {
    int e = blockIdx.x * blockDim.x + threadIdx.x;
    if (e < E) {
        int d = load_idx(ew, E, e, 1);
        if ((unsigned)d < (unsigned)N) atomicAdd(&g_cnt[d], 1);
    }
}

// single-block sequential-chunk scan: row_ptr = exclusive scan of cnt
__global__ void scan_k(int N) {
    __shared__ int sh[2][1024];
    int tid = threadIdx.x;
    int carry = 0;
    if (tid == 0) g_rowptr[0] = 0;
    for (int base = 0; base < N; base += 1024) {
        int v = (base + tid < N) ? g_cnt[base + tid] : 0;
        sh[0][tid] = v;
        __syncthreads();
        int pin = 0;
        #pragma unroll
        for (int off = 1; off < 1024; off <<= 1) {
            int t = sh[pin][tid] + ((tid >= off) ? sh[pin][tid - off] : 0);
            sh[pin ^ 1][tid] = t;
            pin ^= 1;
            __syncthreads();
        }
        int incl = sh[pin][tid];
        if (base + tid < N) g_rowptr[base + tid + 1] = carry + incl;
        carry += sh[pin][1023];
        __syncthreads();
    }
}

__global__ void init2_k(int N) {
    int i = blockIdx.x * blockDim.x + threadIdx.x;
    if (i < N) {
        g_cursor[i] = g_rowptr[i];
        // degree includes the self-loop (+1); always > 0
        g_dinv[i] = rsqrtf((float)g_cnt[i] + 1.0f);
    }
}

__global__ void fill_k(const int* __restrict__ ew, int E, int N) {
    int e = blockIdx.x * blockDim.x + threadIdx.x;
    if (e < E) {
        int d = load_idx(ew, E, e, 1);
        int s = load_idx(ew, E, e, 0);
        if ((unsigned)d < (unsigned)N && (unsigned)s < (unsigned)N) {
            int pos = atomicAdd(&g_cursor[d], 1);
            g_srccsr[pos] = s;
        }
    }
}

// ---------------- fp32 GEMM: C[M,128] = A[M,128] @ W[128,128], fused epilogue ----------------
// a_sel: 0 -> Aext, 1 -> g_bufA.  c_sel: 0 -> g_bufA, 1 -> g_bufB.
// epilogue: c = acc * (rowscale? dinv[row] : 1) (+ bias[col] if has_bias) (relu if relu_f)
__global__ __launch_bounds__(256, 2)
void gemm_k128(const float* __restrict__ Aext, int a_sel,
               const float* __restrict__ W,
               const float* __restrict__ bias, int has_bias,
               int relu_f, int rowscale_f, int c_sel, int M)
{
    __shared__ __align__(16) float As[16][132];  // [k][m], padded (132*4 = 16B-aligned rows)
    __shared__ __align__(16) float Ws[16][128];  // [k][n]
    const float* A = a_sel ? g_bufA : Aext;
    float* C = c_sel ? g_bufB : g_bufA;

    int tid = threadIdx.x;
    int tx = tid & 15, ty = tid >> 4;     // 16x16 thread grid, 8x8 micro-tile
    int blockRow = blockIdx.x * 128;

    float acc[8][8];
    #pragma unroll
    for (int i = 0; i < 8; i++)
        #pragma unroll
        for (int j = 0; j < 8; j++) acc[i][j] = 0.0f;

    for (int k0 = 0; k0 < 128; k0 += 16) {
        #pragma unroll
        for (int it = 0; it < 2; it++) {
            int lin = tid + it * 256;      // 0..511
            int r = lin >> 2;              // 0..127
            int c4 = lin & 3;              // 0..3
            int grow = blockRow + r;
            float4 v = make_float4(0.f, 0.f, 0.f, 0.f);
            if (grow < M) v = *(const float4*)(A + (size_t)grow * 128 + k0 + c4 * 4);
            As[c4 * 4 + 0][r] = v.x;
            As[c4 * 4 + 1][r] = v.y;
            As[c4 * 4 + 2][r] = v.z;
            As[c4 * 4 + 3][r] = v.w;
        }
        #pragma unroll
        for (int it = 0; it < 2; it++) {
            int lin = tid + it * 256;
            int kr = lin >> 5;             // 0..15
            int c4 = lin & 31;             // 0..31
            *(float4*)&Ws[kr][c4 * 4] =
                *(const float4*)(W + (size_t)(k0 + kr) * 128 + c4 * 4);
        }
        __syncthreads();
        #pragma unroll
        for (int k = 0; k < 16; k++) {
            float a[8], b[8];
            *(float4*)&a[0] = *(const float4*)&As[k][ty * 8];
            *(float4*)&a[4] = *(const float4*)&As[k][ty * 8 + 4];
            *(float4*)&b[0] = *(const float4*)&Ws[k][tx * 8];
            *(float4*)&b[4] = *(const float4*)&Ws[k][tx * 8 + 4];
            #pragma unroll
            for (int i = 0; i < 8; i++)
                #pragma unroll
                for (int j = 0; j < 8; j++)
                    acc[i][j] = fmaf(a[i], b[j], acc[i][j]);
        }
        __syncthreads();
    }

    #pragma unroll
    for (int i = 0; i < 8; i++) {
        int grow = blockRow + ty * 8 + i;
        if (grow >= M) continue;
        float rs = rowscale_f ? g_dinv[grow] : 1.0f;
        float o[8];
        #pragma unroll
        for (int j = 0; j < 8; j++) o[j] = acc[i][j] * rs;
        if (has_bias) {
            #pragma unroll
            for (int j = 0; j < 8; j++) o[j] += bias[tx * 8 + j];
        }
        if (relu_f) {
            #pragma unroll
            for (int j = 0; j < 8; j++) o[j] = fmaxf(o[j], 0.0f);
        }
        *(float4*)(C + (size_t)grow * 128 + tx * 8)     = *(float4*)&o[0];
        *(float4*)(C + (size_t)grow * 128 + tx * 8 + 4) = *(float4*)&o[4];
    }
}

// ---------------- pull aggregation: one warp per node ----------------
// bufA[i] = relu( dinv[i] * ( hs[i] + sum_{e: dst=i} hs[src_e] ) + gcnb[c] )
// where hs rows already carry dinv[src] (applied in GEMM epilogue).
__global__ __launch_bounds__(256)
void agg_k(const float* __restrict__ gcnb, int M)
{
    int warp = (blockIdx.x * 256 + threadIdx.x) >> 5;
    int lane = threadIdx.x & 31;
    if (warp >= M) return;
    const float4* __restrict__ hs = (const float4*)g_bufB;

    float4 s0 = hs[(size_t)warp * 32 + lane];   // self loop
    float4 s1 = make_float4(0.f, 0.f, 0.f, 0.f);
    float4 s2 = s1, s3 = s1;

    int e = g_rowptr[warp];
    int end = g_rowptr[warp + 1];
    for (; e + 4 <= end; e += 4) {
        int i0 = g_srccsr[e + 0];
        int i1 = g_srccsr[e + 1];
        int i2 = g_srccsr[e + 2];
        int i3 = g_srccsr[e + 3];
        float4 v0 = hs[(size_t)i0 * 32 + lane];
        float4 v1 = hs[(size_t)i1 * 32 + lane];
        float4 v2 = hs[(size_t)i2 * 32 + lane];
        float4 v3 = hs[(size_t)i3 * 32 + lane];
        s0.x += v0.x; s0.y += v0.y; s0.z += v0.z; s0.w += v0.w;
        s1.x += v1.x; s1.y += v1.y; s1.z += v1.z; s1.w += v1.w;
        s2.x += v2.x; s2.y += v2.y; s2.z += v2.z; s2.w += v2.w;
        s3.x += v3.x; s3.y += v3.y; s3.z += v3.z; s3.w += v3.w;
    }
    for (; e < end; e++) {
        int i = g_srccsr[e];
        float4 v = hs[(size_t)i * 32 + lane];
        s0.x += v.x; s0.y += v.y; s0.z += v.z; s0.w += v.w;
    }

    float di = g_dinv[warp];
    float4 b = ((const float4*)gcnb)[lane];
    float4 o;
    o.x = fmaxf(fmaf(di, s0.x + s1.x + s2.x + s3.x, b.x), 0.0f);
    o.y = fmaxf(fmaf(di, s0.y + s1.y + s2.y + s3.y, b.y), 0.0f);
    o.z = fmaxf(fmaf(di, s0.z + s1.z + s2.z + s3.z, b.z), 0.0f);
    o.w = fmaxf(fmaf(di, s0.w + s1.w + s2.w + s3.w, b.w), 0.0f);
    ((float4*)g_bufA)[(size_t)warp * 32 + lane] = o;
}

// ---------------- lin2 + log_softmax fused: one warp per row ----------------
__global__ __launch_bounds__(256)
void lin2_softmax_k(const float* __restrict__ W2,   // [128,40]
                    const float* __restrict__ b2,   // [40]
                    float* __restrict__ out, int M)
{
    __shared__ float Ws[40][132];   // Ws[c][k] = W2[k*40+c]
    __shared__ float sb2[40];
    int tid = threadIdx.x;
    for (int i = tid; i < 40 * 128; i += 256) {
        int k = i / 40, c = i % 40;
        Ws[c][k] = W2[i];
    }
    if (tid < 40) sb2[tid] = b2[tid];
    __syncthreads();

    int lane = tid & 31, wid = tid >> 5;
    for (int row = blockIdx.x * 8 + wid; row < M; row += gridDim.x * 8) {
        const float* h = g_bufA + (size_t)row * 128;
        float a0 = h[lane];
        float a1 = h[lane + 32];
        float a2 = h[lane + 64];
        float a3 = h[lane + 96];

        float m = -1e30f;
        float v0 = 0.0f, v1 = 0.0f;   // logits for cols lane and lane+32
        #pragma unroll 8
        for (int c = 0; c < 40; c++) {
            float p = a0 * Ws[c][lane] + a1 * Ws[c][lane + 32]
                    + a2 * Ws[c][lane + 64] + a3 * Ws[c][lane + 96];
            #pragma unroll
            for (int off = 16; off > 0; off >>= 1)
                p += __shfl_xor_sync(0xffffffffu, p, off);
            p += sb2[c];
            if (c == lane) v0 = p;
            if (c == lane + 32) v1 = p;
            m = fmaxf(m, p);
        }
        float se = expf(v0 - m) + ((lane < 8) ? expf(v1 - m) : 0.0f);
        #pragma unroll
        for (int off = 16; off > 0; off >>= 1)
            se += __shfl_xor_sync(0xffffffffu, se, off);
        float lse = m + logf(se);
        out[(size_t)row * 40 + lane] = v0 - lse;
        if (lane < 8) out[(size_t)row * 40 + 32 + lane] = v1 - lse;
    }
}

// ---------------- launch ----------------
extern "C" void kernel_launch(void* const* d_in, const int* in_sizes, int n_in,
                              void* d_out, int out_size)
{
    const float* x  = (const float*)d_in[0];
    const int*   ew = (const int*)d_in[1];       // edge_index as 32-bit words (int32 or int64 storage)
    const float* w1 = (const float*)d_in[2];
    const float* b1 = (const float*)d_in[3];
    const float* gw = (const float*)d_in[4];     // [3,128,128]
    const float* gb = (const float*)d_in[5];     // [3,128]
    const float* w2 = (const float*)d_in[6];     // [128,40]
    const float* b2 = (const float*)d_in[7];     // [40]
    float* out = (float*)d_out;

    int N = in_sizes[0] / HIDC;
    int E = in_sizes[1] / 2;                     // element count is dtype-independent

    int nb_n = (N + 255) / 256;
    int nb_e = (E + 255) / 256;
    int gemm_blocks = (N + 127) / 128;
    int warp_blocks = (N + 7) / 8;

    // detect int32 vs int64 edge_index storage (device-side flag)
    detect_k<<<1, 256>>>((const unsigned int*)ew, E);

    // CSR-by-dst build + symmetric-norm dinv
    zero_cnt_k<<<nb_n, 256>>>(N);
    count_k<<<nb_e, 256>>>(ew, E, N);
    scan_k<<<1, 1024>>>(N);
    init2_k<<<nb_n, 256>>>(N);
    fill_k<<<nb_e, 256>>>(ew, E, N);

    // lin1: bufA = relu(x @ w1 + b1)
    gemm_k128<<<gemm_blocks, 256>>>(x, 0, w1, b1, /*has_bias*/1, /*relu*/1,
                                    /*rowscale*/0, /*c_sel*/0, N);
    // 3 GCN layers
    for (int k = 0; k < 3; k++) {
        // bufB = (bufA @ gcn_w[k]) * dinv[row]
        gemm_k128<<<gemm_blocks, 256>>>(nullptr, 1, gw + (size_t)k * 128 * 128,
                                        nullptr, 0, 0, /*rowscale*/1, /*c_sel*/1, N);
        // bufA = relu(dinv * (self + neighbor sum) + gcn_b[k])
        agg_k<<<warp_blocks, 256>>>(gb + (size_t)k * 128, N);
    }
    // logits + log_softmax
    lin2_softmax_k<<<warp_blocks, 256>>>(w2, b2, out, N);
}